// round 16
// baseline (speedup 1.0000x reference)
#include <cuda_runtime.h>
#include <math.h>
#include <stdint.h>

#define BB   2
#define HH   16
#define TT   2048
#define DH   64
#define DD   1024
#define NC   16      // candidates carried into fp64 re-rank (k=8 + 8 margin, tf32 filter)
#define JT   128     // key rows per attention tile
#define QR   128     // query rows per attention CTA (8 warps x 16 rows)
#define KP   68      // smem row pitch in floats
#define ATHREADS 256

// -------- scratch (device globals; no allocation allowed) --------
__device__ float g_q[BB*HH*TT*DH];
__device__ float g_k[BB*HH*TT*DH];
__device__ float g_v[BB*HH*TT*DH];
__device__ float g_att[BB*TT*DD];

// ============================================================================
// SGEMM (NT): C[m][n] = sum_k A[m][k] * B[n][k]
// BM=BN=128, BK=16, 256 threads, 8x8 per thread. (Proven-fastest R10 variant,
// verbatim. Two-level accumulation keeps q/k within ~1e-7 of the reference so
// the top-k selection does not flip.) FP32 on purpose: selection correctness
// depends on q/k accuracy.
// A == nullptr  -> read A from the device-global g_att (out-proj input).
// scatter == 1  -> QKV projection: scatter into g_q/g_k/g_v, head-split layout.
// ============================================================================
__global__ __launch_bounds__(256)
void sgemm_nt(const float* __restrict__ A, const float* __restrict__ B,
              float* __restrict__ C, int M, int N, int K, int scatter)
{
    __shared__ float As[16][132];
    __shared__ float Bs[16][132];

    const float* Abase = A ? A : (const float*)g_att;

    const int tid = threadIdx.x;
    const int m0  = blockIdx.y * 128;
    const int n0  = blockIdx.x * 128;
    const int tx  = tid & 15;
    const int ty  = tid >> 4;
    const int lr  = tid >> 2;          // 0..63
    const int lc  = (tid & 3) << 2;    // 0,4,8,12

    float acc[8][8];
    float cacc[8][8];
    #pragma unroll
    for (int i = 0; i < 8; i++)
        #pragma unroll
        for (int j = 0; j < 8; j++) { acc[i][j] = 0.f; cacc[i][j] = 0.f; }

    const float* Ap = Abase + (size_t)(m0 + lr) * K + lc;
    const float* Bp = B     + (size_t)(n0 + lr) * K + lc;

    for (int k0 = 0; k0 < K; k0 += 16) {
        float4 a0 = *(const float4*)(Ap + k0);
        float4 a1 = *(const float4*)(Ap + (size_t)64 * K + k0);
        float4 b0 = *(const float4*)(Bp + k0);
        float4 b1 = *(const float4*)(Bp + (size_t)64 * K + k0);
        __syncthreads();
        As[lc+0][lr]    = a0.x; As[lc+1][lr]    = a0.y; As[lc+2][lr]    = a0.z; As[lc+3][lr]    = a0.w;
        As[lc+0][lr+64] = a1.x; As[lc+1][lr+64] = a1.y; As[lc+2][lr+64] = a1.z; As[lc+3][lr+64] = a1.w;
        Bs[lc+0][lr]    = b0.x; Bs[lc+1][lr]    = b0.y; Bs[lc+2][lr]    = b0.z; Bs[lc+3][lr]    = b0.w;
        Bs[lc+0][lr+64] = b1.x; Bs[lc+1][lr+64] = b1.y; Bs[lc+2][lr+64] = b1.z; Bs[lc+3][lr+64] = b1.w;
        __syncthreads();

        #pragma unroll
        for (int kk = 0; kk < 16; kk++) {
            float a[8], b[8];
            *(float4*)&a[0] = *(const float4*)&As[kk][ty*8];
            *(float4*)&a[4] = *(const float4*)&As[kk][ty*8 + 4];
            *(float4*)&b[0] = *(const float4*)&Bs[kk][tx*8];
            *(float4*)&b[4] = *(const float4*)&Bs[kk][tx*8 + 4];
            #pragma unroll
            for (int i = 0; i < 8; i++)
                #pragma unroll
                for (int j = 0; j < 8; j++)
                    cacc[i][j] = fmaf(a[i], b[j], cacc[i][j]);
        }

        if (k0 & 16) {   // flush every 32 k-steps (K % 32 == 0)
            #pragma unroll
            for (int i = 0; i < 8; i++)
                #pragma unroll
                for (int j = 0; j < 8; j++) { acc[i][j] += cacc[i][j]; cacc[i][j] = 0.f; }
        }
    }

    if (!scatter) {
        #pragma unroll
        for (int i = 0; i < 8; i++) {
            float* cp = C + (size_t)(m0 + ty*8 + i) * N + n0 + tx*8;
            *(float4*)cp       = make_float4(acc[i][0], acc[i][1], acc[i][2], acc[i][3]);
            *(float4*)(cp + 4) = make_float4(acc[i][4], acc[i][5], acc[i][6], acc[i][7]);
        }
    } else {
        #pragma unroll
        for (int i = 0; i < 8; i++) {
            int t  = m0 + ty*8 + i;
            int b_ = t >> 11;          // /2048
            int tl = t & 2047;
            #pragma unroll
            for (int j = 0; j < 8; j++) {
                int o    = n0 + tx*8 + j;
                int part = o >> 10;        // 0=q 1=k 2=v
                int rem  = o & 1023;
                int h    = rem >> 6;
                int dhi  = rem & 63;
                float* dst = (part == 0) ? g_q : (part == 1) ? g_k : g_v;
                dst[(((size_t)(b_*HH + h)) * TT + tl) * DH + dhi] = acc[i][j];
            }
        }
    }
}

// ============================================================================
// Fused causal scores (TF32 tensor cores) + top-k filter + fp64 re-rank
// + softmax + sparse AV.
// CTA: 256 threads = 8 warps; warp w owns 16 query rows (qrow0 = row0+16w).
// K tiles: 128 rows x 64 dims, cp.async double-buffered in smem.
// Per warp per tile: 16 n8-blocks x 8 k-chunks of mma.sync.m16n8k8 tf32.
// Each thread owns score elements of 2 rows (tq, tq+8) x 2 cols per block;
// it keeps a packed (score | 11-bit col index) top-8 per row. Per-row merge
// across the 4 owning lanes yields top-16 candidates; fp64 exact recompute
// (full-precision q,k from gmem) decides the final top-8 -> tf32/packing
// noise only affects the candidate pool, never the selection.
// Grid: (32 = B*H, 16 = T/128), heavy tiles first.
// Partial unrolls (4x mainloop, 2x merge) keep the ptxas compile unit small.
// ============================================================================
__device__ __forceinline__ void cp16(unsigned saddr, const void* gptr)
{
    asm volatile("cp.async.cg.shared.global [%0], [%1], 16;\n" :: "r"(saddr), "l"(gptr));
}

__device__ __forceinline__ void mma_tf32(float& c0, float& c1, float& c2, float& c3,
                                         unsigned a0, unsigned a1, unsigned a2, unsigned a3,
                                         unsigned b0, unsigned b1)
{
    asm volatile("mma.sync.aligned.m16n8k8.row.col.f32.tf32.tf32.f32 "
                 "{%0,%1,%2,%3}, {%4,%5,%6,%7}, {%8,%9}, {%0,%1,%2,%3};\n"
                 : "+f"(c0), "+f"(c1), "+f"(c2), "+f"(c3)
                 : "r"(a0), "r"(a1), "r"(a2), "r"(a3), "r"(b0), "r"(b1));
}

__device__ __forceinline__ void ins8(float tv[8], float pf)
{
    if (pf > tv[7]) {
        float cv = pf;
        #pragma unroll
        for (int p = 0; p < 8; p++)
            if (cv > tv[p]) { float t = tv[p]; tv[p] = cv; cv = t; }
    }
}

__global__ __launch_bounds__(ATHREADS)
void attn_topk_kernel()
{
    extern __shared__ float sm[];
    float* const ks0 = sm;               // [JT][KP]
    float* const ks1 = sm + JT * KP;     // [JT][KP]

    const int bh   = blockIdx.x;
    const int qt   = (int)gridDim.y - 1 - (int)blockIdx.y;  // heavy tiles first
    const int row0 = qt * QR;
    const int tid  = threadIdx.x;
    const int wid  = tid >> 5;           // 0..7
    const int lane = tid & 31;
    const int tq   = lane >> 2;          // 0..7
    const int tk   = lane & 3;           // 0..3

    const float* Qb = g_q + (size_t)bh * TT * DH;
    const float* Kb = g_k + (size_t)bh * TT * DH;
    const float* Vb = g_v + (size_t)bh * TT * DH;

    const int qrow0 = row0 + wid * 16;
    const int gi_lo = qrow0 + tq;        // thread's low row (global)
    const int gi_hi = gi_lo + 8;         // thread's high row (global)

    const int ntiles = qt + 1;           // QR == JT == 128

    // prologue: cp.async K tile 0 into ks0 (8 x 16B per thread)
    #pragma unroll
    for (int i = 0; i < 8; i++) {
        int ii = tid + ATHREADS * i;
        int r = ii >> 4, c = (ii & 15) << 2;
        cp16((unsigned)__cvta_generic_to_shared(&ks0[r * KP + c]),
             Kb + (size_t)r * DH + c);
    }
    asm volatile("cp.async.commit_group;\n");

    // A fragments: warp's 16 Q rows x 64 dims, scaled by 1/8 (exact), 8 k-chunks
    unsigned af[8][4];
    #pragma unroll
    for (int ck = 0; ck < 8; ck++) {
        int c0 = ck * 8 + tk;
        af[ck][0] = __float_as_uint(0.125f * Qb[(size_t)(qrow0 + tq    ) * DH + c0    ]);
        af[ck][1] = __float_as_uint(0.125f * Qb[(size_t)(qrow0 + tq + 8) * DH + c0    ]);
        af[ck][2] = __float_as_uint(0.125f * Qb[(size_t)(qrow0 + tq    ) * DH + c0 + 4]);
        af[ck][3] = __float_as_uint(0.125f * Qb[(size_t)(qrow0 + tq + 8) * DH + c0 + 4]);
    }

    const float SENT = __uint_as_float(0xFF000000u);   // huge negative, idx bits 0
    float tv0[8], tv1[8];
    #pragma unroll
    for (int p = 0; p < 8; p++) { tv0[p] = SENT; tv1[p] = SENT; }

    for (int tj = 0; tj < ntiles; tj++) {
        const int j0 = tj * JT;
        const float* kb = (tj & 1) ? ks1 : ks0;

        if (tj + 1 < ntiles) {
            float* nb = (tj & 1) ? ks0 : ks1;
            const int jn = (tj + 1) * JT;
            #pragma unroll
            for (int i = 0; i < 8; i++) {
                int ii = tid + ATHREADS * i;
                int r = ii >> 4, c = (ii & 15) << 2;
                cp16((unsigned)__cvta_generic_to_shared(&nb[r * KP + c]),
                     Kb + (size_t)(jn + r) * DH + c);
            }
            asm volatile("cp.async.commit_group;\n");
            asm volatile("cp.async.wait_group 1;\n");   // tile tj resident
        } else {
            asm volatile("cp.async.wait_group 0;\n");
        }
        __syncthreads();

        if (j0 <= qrow0 + 15) {         // warp has at least one causal column here
            #pragma unroll 4
            for (int blk = 0; blk < 16; blk++) {
                float c0 = 0.f, c1 = 0.f, c2 = 0.f, c3 = 0.f;
                const float* kr = kb + (blk * 8 + tq) * KP;
                #pragma unroll
                for (int ck = 0; ck < 8; ck++) {
                    unsigned b0 = __float_as_uint(kr[ck * 8 + tk]);
                    unsigned b1 = __float_as_uint(kr[ck * 8 + tk + 4]);
                    mma_tf32(c0, c1, c2, c3,
                             af[ck][0], af[ck][1], af[ck][2], af[ck][3], b0, b1);
                }
                const int jc = j0 + blk * 8 + 2 * tk;
                // pack column index into low 11 mantissa bits; causal-guarded insert
                if (jc <= gi_lo)
                    ins8(tv0, __uint_as_float((__float_as_uint(c0) & 0xFFFFF800u) | (unsigned)jc));
                if (jc + 1 <= gi_lo)
                    ins8(tv0, __uint_as_float((__float_as_uint(c1) & 0xFFFFF800u) | (unsigned)(jc + 1)));
                if (jc <= gi_hi)
                    ins8(tv1, __uint_as_float((__float_as_uint(c2) & 0xFFFFF800u) | (unsigned)jc));
                if (jc + 1 <= gi_hi)
                    ins8(tv1, __uint_as_float((__float_as_uint(c3) & 0xFFFFF800u) | (unsigned)(jc + 1)));
            }
        }
        __syncthreads();   // all warps done with kb before next-iter cp.async overwrites it
    }

    // ---- parallel per-row-group merges: 4 lanes x top-8 -> top-16 per row ----
    // group of row r (warp-local, r<8): lanes 4r..4r+3; all 4 compute identical mi.
    int miA[NC], miB[NC];
    #pragma unroll 2
    for (int n = 0; n < NC; n++) {
        float head = tv0[0];
        float m1   = fmaxf(head, __shfl_xor_sync(0xffffffffu, head, 1));
        float best = fmaxf(m1,   __shfl_xor_sync(0xffffffffu, m1,   2));
        miA[n] = (best < -1.0e37f) ? -1 : (int)(__float_as_uint(best) & 2047u);
        if (head == best) {            // unique packed values -> exactly one popper
            #pragma unroll
            for (int p = 0; p < 7; p++) tv0[p] = tv0[p + 1];
            tv0[7] = SENT;
        }
    }
    #pragma unroll 2
    for (int n = 0; n < NC; n++) {
        float head = tv1[0];
        float m1   = fmaxf(head, __shfl_xor_sync(0xffffffffu, head, 1));
        float best = fmaxf(m1,   __shfl_xor_sync(0xffffffffu, m1,   2));
        miB[n] = (best < -1.0e37f) ? -1 : (int)(__float_as_uint(best) & 2047u);
        if (head == best) {
            #pragma unroll
            for (int p = 0; p < 7; p++) tv1[p] = tv1[p + 1];
            tv1[7] = SENT;
        }
    }

    const int b_ = bh >> 4;
    const int h  = bh & 15;

    // ---- per row: fp64 exact re-rank, softmax over kept, sparse AV ----
    #pragma unroll 1
    for (int R = 0; R < 16; R++) {
        const int g   = R & 7;
        const int src = g * 4;
        const int gi  = qrow0 + R;

        int mi[NC];
        #pragma unroll
        for (int n = 0; n < NC; n++)
            mi[n] = __shfl_sync(0xffffffffu, (R < 8) ? miA[n] : miB[n], src);

        // exact scores from FULL-precision gmem q,k (not the tf32 filter operands)
        float q1 = Qb[(size_t)gi * DH + lane];
        float q2 = Qb[(size_t)gi * DH + lane + 32];
        double dv[NC];
        #pragma unroll
        for (int n = 0; n < NC; n++) {
            int j = mi[n];
            double p = 0.0;
            if (j >= 0) {
                const float* kr = Kb + (size_t)j * DH;
                p = (double)q1 * (double)kr[lane] + (double)q2 * (double)kr[lane + 32];
            }
            #pragma unroll
            for (int off = 16; off > 0; off >>= 1)
                p += __shfl_xor_sync(0xffffffffu, p, off);
            dv[n] = (j >= 0) ? p * 0.125 : -1.0e300;   // /8 scale, exact in fp64
        }

        int keff = min(gi + 1, 8);
        double mx = dv[0];
        #pragma unroll
        for (int n = 1; n < NC; n++) if (dv[n] > mx) mx = dv[n];

        float w[NC];
        float den = 0.f;
        #pragma unroll
        for (int n = 0; n < NC; n++) {
            int rank = 0;
            #pragma unroll
            for (int m = 0; m < NC; m++) rank += (dv[m] > dv[n]) ? 1 : 0;
            bool keep = (mi[n] >= 0) && (rank < keff);
            float wn = keep ? __expf((float)(dv[n] - mx)) : 0.f;
            w[n] = wn;
            den += wn;
        }

        float o0 = 0.f, o1 = 0.f;
        #pragma unroll
        for (int n = 0; n < NC; n++) {
            if (w[n] > 0.f) {   // uniform across warp (mi, dv identical on all lanes)
                const float* vr = Vb + (size_t)mi[n] * DH;
                o0 = fmaf(w[n], vr[lane],      o0);
                o1 = fmaf(w[n], vr[lane + 32], o1);
            }
        }
        float inv = 1.f / den;
        float* op = g_att + ((size_t)b_ * TT + gi) * DD + h * DH;
        op[lane]      = o0 * inv;
        op[lane + 32] = o1 * inv;
    }
}

// ============================================================================
// launch — kernel launches only (plus one idempotent, non-stream attribute
// call for the >48KB dynamic smem opt-in; legal under graph capture).
// ============================================================================
extern "C" void kernel_launch(void* const* d_in, const int* in_sizes, int n_in,
                              void* d_out, int out_size)
{
    const float* x     = (const float*)d_in[0];   // (2,2048,1024)
    const float* w_qkv = (const float*)d_in[1];   // (3072,1024)
    const float* w_out = (const float*)d_in[2];   // (1024,1024)
    float* out = (float*)d_out;                   // (2,2048,1024)

    const int ATTN_SMEM = 2 * JT * KP * (int)sizeof(float);   // 69632 B
    cudaFuncSetAttribute(attn_topk_kernel,
                         cudaFuncAttributeMaxDynamicSharedMemorySize, ATTN_SMEM);

    dim3 blk(256);
    // QKV projection + head-split scatter: M=4096, N=3072, K=1024
    sgemm_nt<<<dim3(3072 / 128, 4096 / 128), blk>>>(x, w_qkv, nullptr, 4096, 3072, 1024, 1);
    // fused TF32 scores + top-k filter + fp64 re-rank + softmax + sparse AV
    attn_topk_kernel<<<dim3(BB * HH, TT / QR), ATHREADS, ATTN_SMEM>>>();
    // output projection: M=4096, N=1024, K=1024  (A = g_att via nullptr)
    sgemm_nt<<<dim3(1024 / 128, 4096 / 128), blk>>>(nullptr, w_out, out, 4096, 1024, 1024, 0);
}

// round 17
// speedup vs baseline: 2.0565x; 2.0565x over previous
#include <cuda_runtime.h>
#include <math.h>

#define BB   2
#define HH   16
#define TT   2048
#define DH   64
#define DD   1024
#define NC   10      // candidates carried into fp64 re-rank (k=8 + 2 margin)

// -------- scratch (device globals; no allocation allowed) --------
__device__ float g_q[BB*HH*TT*DH];
__device__ float g_k[BB*HH*TT*DH];
__device__ float g_v[BB*HH*TT*DH];
__device__ float g_att[BB*TT*DD];

typedef unsigned long long u64;

// ---- packed fp32x2 helpers (B300: FFMA2 only reachable via PTX) ----
__device__ __forceinline__ u64 pack2(float x, float y) {
    u64 r; asm("mov.b64 %0, {%1, %2};" : "=l"(r) : "f"(x), "f"(y)); return r;
}
__device__ __forceinline__ void fma2(u64& c, u64 a, u64 b) {
    asm("fma.rn.f32x2 %0, %1, %2, %0;" : "+l"(c) : "l"(a), "l"(b));
}
__device__ __forceinline__ void add2(u64& c, u64 a) {
    asm("add.rn.f32x2 %0, %0, %1;" : "+l"(c) : "l"(a));
}
__device__ __forceinline__ float2 unpack2(u64 v) {
    float2 f; asm("mov.b64 {%0, %1}, %2;" : "=f"(f.x), "=f"(f.y) : "l"(v)); return f;
}

// ============================================================================
// SGEMM (NT): C[m][n] = sum_k A[m][k] * B[n][k]
// BM=BN=128, BK=16, 256 threads, 8x8 per thread. Structure of the proven
// 734us variant (prologue load + prefetch-next inside compute); inner loop
// now uses packed fma.rn.f32x2 (2 columns per instruction). Per-element
// arithmetic is bitwise identical to the scalar version (independent fp32
// FMAs, independent column accumulators), so q/k and the downstream top-k
// selection are unchanged. Two-level accumulation (flush every 32 k-steps).
// A == nullptr  -> read A from the device-global g_att (out-proj input).
// scatter == 1  -> QKV projection: scatter into g_q/g_k/g_v, head-split layout.
// ============================================================================
__global__ __launch_bounds__(256)
void sgemm_nt(const float* __restrict__ A, const float* __restrict__ B,
              float* __restrict__ C, int M, int N, int K, int scatter)
{
    __shared__ float As[16][132];
    __shared__ float Bs[16][132];

    const float* Abase = A ? A : (const float*)g_att;

    const int tid = threadIdx.x;
    const int m0  = blockIdx.y * 128;
    const int n0  = blockIdx.x * 128;
    const int tx  = tid & 15;
    const int ty  = tid >> 4;
    const int lr  = tid >> 2;          // 0..63
    const int lc  = (tid & 3) << 2;    // 0,4,8,12

    u64 acc2[8][4];                    // packed column pairs (2j, 2j+1)
    u64 cacc2[8][4];
    #pragma unroll
    for (int i = 0; i < 8; i++)
        #pragma unroll
        for (int j = 0; j < 4; j++) { acc2[i][j] = 0ull; cacc2[i][j] = 0ull; }

    const float* Ap = Abase + (size_t)(m0 + lr) * K + lc;
    const float* Bp = B     + (size_t)(n0 + lr) * K + lc;

    // prologue: load first k-tile into registers
    float4 a0 = *(const float4*)(Ap);
    float4 a1 = *(const float4*)(Ap + (size_t)64 * K);
    float4 b0 = *(const float4*)(Bp);
    float4 b1 = *(const float4*)(Bp + (size_t)64 * K);

    for (int k0 = 0; k0 < K; k0 += 16) {
        __syncthreads();   // previous tile's compute done
        As[lc+0][lr]    = a0.x; As[lc+1][lr]    = a0.y; As[lc+2][lr]    = a0.z; As[lc+3][lr]    = a0.w;
        As[lc+0][lr+64] = a1.x; As[lc+1][lr+64] = a1.y; As[lc+2][lr+64] = a1.z; As[lc+3][lr+64] = a1.w;
        Bs[lc+0][lr]    = b0.x; Bs[lc+1][lr]    = b0.y; Bs[lc+2][lr]    = b0.z; Bs[lc+3][lr]    = b0.w;
        Bs[lc+0][lr+64] = b1.x; Bs[lc+1][lr+64] = b1.y; Bs[lc+2][lr+64] = b1.z; Bs[lc+3][lr+64] = b1.w;
        __syncthreads();

        // prefetch next tile (hidden under compute)
        int kn = k0 + 16;
        if (kn < K) {
            a0 = *(const float4*)(Ap + kn);
            a1 = *(const float4*)(Ap + (size_t)64 * K + kn);
            b0 = *(const float4*)(Bp + kn);
            b1 = *(const float4*)(Bp + (size_t)64 * K + kn);
        }

        #pragma unroll
        for (int kk = 0; kk < 16; kk++) {
            float a[8];
            *(float4*)&a[0] = *(const float4*)&As[kk][ty*8];
            *(float4*)&a[4] = *(const float4*)&As[kk][ty*8 + 4];
            // b column pairs straight from smem (8-float contiguous, 16B aligned)
            ulonglong2 t0 = *(const ulonglong2*)&Bs[kk][tx*8];
            ulonglong2 t1 = *(const ulonglong2*)&Bs[kk][tx*8 + 4];
            u64 bp0 = t0.x, bp1 = t0.y, bp2 = t1.x, bp3 = t1.y;
            #pragma unroll
            for (int i = 0; i < 8; i++) {
                u64 as2 = pack2(a[i], a[i]);
                fma2(cacc2[i][0], as2, bp0);
                fma2(cacc2[i][1], as2, bp1);
                fma2(cacc2[i][2], as2, bp2);
                fma2(cacc2[i][3], as2, bp3);
            }
        }

        if (k0 & 16) {   // flush every 32 k-steps (K % 32 == 0)
            #pragma unroll
            for (int i = 0; i < 8; i++)
                #pragma unroll
                for (int j = 0; j < 4; j++) { add2(acc2[i][j], cacc2[i][j]); cacc2[i][j] = 0ull; }
        }
    }

    // unpack accumulators
    float acc[8][8];
    #pragma unroll
    for (int i = 0; i < 8; i++)
        #pragma unroll
        for (int j = 0; j < 4; j++) {
            float2 p = unpack2(acc2[i][j]);
            acc[i][2*j]     = p.x;
            acc[i][2*j + 1] = p.y;
        }

    if (!scatter) {
        #pragma unroll
        for (int i = 0; i < 8; i++) {
            float* cp = C + (size_t)(m0 + ty*8 + i) * N + n0 + tx*8;
            *(float4*)cp       = make_float4(acc[i][0], acc[i][1], acc[i][2], acc[i][3]);
            *(float4*)(cp + 4) = make_float4(acc[i][4], acc[i][5], acc[i][6], acc[i][7]);
        }
    } else {
        #pragma unroll
        for (int i = 0; i < 8; i++) {
            int t  = m0 + ty*8 + i;
            int b_ = t >> 11;          // /2048
            int tl = t & 2047;
            #pragma unroll
            for (int j = 0; j < 8; j++) {
                int o    = n0 + tx*8 + j;
                int part = o >> 10;        // 0=q 1=k 2=v
                int rem  = o & 1023;
                int h    = rem >> 6;
                int dhi  = rem & 63;
                float* dst = (part == 0) ? g_q : (part == 1) ? g_k : g_v;
                dst[(((size_t)(b_*HH + h)) * TT + tl) * DH + dhi] = acc[i][j];
            }
        }
    }
}

// ============================================================================
// Fused causal scores + streaming top-10 + fp64 re-rank + softmax + sparse AV.
// VERBATIM the 2565us-passing version: Grid (32 = B*H, 64 = T/32), 256 thr =
// 8 warps x 4 rows. fp32 streaming scores (32-col K tiles, register prefetch),
// lane-local top-8, warp merge to top-NC, fp64 exact recompute decides the
// final top-8; tie-equivalent softmax; gather of <=8 V rows.
// ============================================================================
__device__ __forceinline__ void topk_insert(float v[8], int ix[8], float s, int j)
{
    float cv = s; int ci = j;
    #pragma unroll
    for (int p = 0; p < 8; p++) {
        if (cv > v[p]) {
            float tvv = v[p]; int tii = ix[p];
            v[p] = cv; ix[p] = ci;
            cv = tvv; ci = tii;
        }
    }
}

__global__ __launch_bounds__(256)
void attn_topk_kernel()
{
    __shared__ float ks[32 * 68];
    __shared__ float qs[32 * 68];

    const int bh   = blockIdx.x;
    const int qt   = (int)gridDim.y - 1 - (int)blockIdx.y;  // heavy tiles first
    const int row0 = qt * 32;
    const int tid  = threadIdx.x;
    const int wid  = tid >> 5;
    const int lane = tid & 31;

    const float* Qb = g_q + (size_t)bh * TT * DH;
    const float* Kb = g_k + (size_t)bh * TT * DH;
    const float* Vb = g_v + (size_t)bh * TT * DH;

    // load Q tile (32 rows x 64) into padded smem
    for (int idx = tid; idx < 32 * 16; idx += 256) {
        int r = idx >> 4, c = (idx & 15) << 2;
        *(float4*)&qs[r * 68 + c] = *(const float4*)(Qb + (size_t)(row0 + r) * DH + c);
    }

    const int rbase = wid * 4;
    const int g0    = row0 + rbase;

    float tv[4][8];
    int   ti[4][8];
    #pragma unroll
    for (int r = 0; r < 4; r++)
        #pragma unroll
        for (int p = 0; p < 8; p++) { tv[r][p] = -INFINITY; ti[r][p] = 0; }

    const float4* qp0 = (const float4*)(qs + (rbase + 0) * 68);
    const float4* qp1 = (const float4*)(qs + (rbase + 1) * 68);
    const float4* qp2 = (const float4*)(qs + (rbase + 2) * 68);
    const float4* qp3 = (const float4*)(qs + (rbase + 3) * 68);
    const float4* kp  = (const float4*)(ks + lane * 68);

    const int ntiles = qt + 1;

    // prologue: prefetch K tile 0 into registers (2 float4 per thread)
    int pr0 = tid >> 4,          pc0 = (tid & 15) << 2;
    int pr1 = (tid + 256) >> 4,  pc1 = ((tid + 256) & 15) << 2;
    float4 rk0 = *(const float4*)(Kb + (size_t)pr0 * DH + pc0);
    float4 rk1 = *(const float4*)(Kb + (size_t)pr1 * DH + pc1);

    for (int tj = 0; tj < ntiles; tj++) {
        int j0 = tj << 5;
        __syncthreads();
        *(float4*)&ks[pr0 * 68 + pc0] = rk0;
        *(float4*)&ks[pr1 * 68 + pc1] = rk1;
        __syncthreads();
        if (tj + 1 < ntiles) {
            int jn = (tj + 1) << 5;
            rk0 = *(const float4*)(Kb + (size_t)(jn + pr0) * DH + pc0);
            rk1 = *(const float4*)(Kb + (size_t)(jn + pr1) * DH + pc1);
        }

        float s0 = 0.f, s1 = 0.f, s2 = 0.f, s3 = 0.f;
        #pragma unroll
        for (int d = 0; d < 16; d++) {
            float4 kv = kp[d];
            float4 q;
            q = qp0[d];
            s0 = fmaf(kv.x, q.x, s0); s0 = fmaf(kv.y, q.y, s0);
            s0 = fmaf(kv.z, q.z, s0); s0 = fmaf(kv.w, q.w, s0);
            q = qp1[d];
            s1 = fmaf(kv.x, q.x, s1); s1 = fmaf(kv.y, q.y, s1);
            s1 = fmaf(kv.z, q.z, s1); s1 = fmaf(kv.w, q.w, s1);
            q = qp2[d];
            s2 = fmaf(kv.x, q.x, s2); s2 = fmaf(kv.y, q.y, s2);
            s2 = fmaf(kv.z, q.z, s2); s2 = fmaf(kv.w, q.w, s2);
            q = qp3[d];
            s3 = fmaf(kv.x, q.x, s3); s3 = fmaf(kv.y, q.y, s3);
            s3 = fmaf(kv.w, q.w, s3); s3 = fmaf(kv.z, q.z, s3);
        }
        int j = j0 + lane;
        s0 *= 0.125f; s1 *= 0.125f; s2 *= 0.125f; s3 *= 0.125f;
        if (j <= g0 + 0 && s0 > tv[0][7]) topk_insert(tv[0], ti[0], s0, j);
        if (j <= g0 + 1 && s1 > tv[1][7]) topk_insert(tv[1], ti[1], s1, j);
        if (j <= g0 + 2 && s2 > tv[2][7]) topk_insert(tv[2], ti[2], s2, j);
        if (j <= g0 + 3 && s3 > tv[3][7]) topk_insert(tv[3], ti[3], s3, j);
    }

    // merge lane-local top-8 -> global top-NC per row, fp64 re-rank, softmax, AV
    const int b_ = bh >> 4;
    const int h  = bh & 15;

    #pragma unroll
    for (int r = 0; r < 4; r++) {
        int gi = g0 + r;
        int mi[NC];
        #pragma unroll
        for (int n = 0; n < NC; n++) {
            float head = tv[r][0];
            float best = head;
            #pragma unroll
            for (int off = 16; off > 0; off >>= 1)
                best = fmaxf(best, __shfl_xor_sync(0xffffffffu, best, off));
            unsigned bal = __ballot_sync(0xffffffffu, head == best);
            int owner = __ffs((int)bal) - 1;
            int idx = __shfl_sync(0xffffffffu, ti[r][0], owner);
            mi[n] = (best == -INFINITY) ? -1 : idx;
            if (lane == owner) {
                #pragma unroll
                for (int p = 0; p < 7; p++) { tv[r][p] = tv[r][p + 1]; ti[r][p] = ti[r][p + 1]; }
                tv[r][7] = -INFINITY;
            }
        }

        // fp64 exact recompute of candidate scores (warp-cooperative)
        const float* qrow = qs + (rbase + r) * 68;
        float q1 = qrow[lane];
        float q2 = qrow[lane + 32];
        double dv[NC];
        #pragma unroll
        for (int n = 0; n < NC; n++) {
            int j = mi[n];
            double p = 0.0;
            if (j >= 0) {
                const float* kr = Kb + (size_t)j * DH;
                p = (double)q1 * (double)kr[lane] + (double)q2 * (double)kr[lane + 32];
            }
            #pragma unroll
            for (int off = 16; off > 0; off >>= 1)
                p += __shfl_xor_sync(0xffffffffu, p, off);
            dv[n] = (j >= 0) ? p * 0.125 : -1.0e300;
        }

        int keff = min(gi + 1, 8);
        double mx = dv[0];
        #pragma unroll
        for (int n = 1; n < NC; n++) if (dv[n] > mx) mx = dv[n];

        float w[NC];
        float den = 0.f;
        #pragma unroll
        for (int n = 0; n < NC; n++) {
            int rank = 0;
            #pragma unroll
            for (int m = 0; m < NC; m++) rank += (dv[m] > dv[n]) ? 1 : 0;
            bool keep = (mi[n] >= 0) && (rank < keff);
            float wn = keep ? __expf((float)(dv[n] - mx)) : 0.f;
            w[n] = wn;
            den += wn;
        }

        float o0 = 0.f, o1 = 0.f;
        #pragma unroll
        for (int n = 0; n < NC; n++) {
            if (w[n] > 0.f) {   // uniform across warp (mi, dv identical on all lanes)
                const float* vr = Vb + (size_t)mi[n] * DH;
                o0 = fmaf(w[n], vr[lane],      o0);
                o1 = fmaf(w[n], vr[lane + 32], o1);
            }
        }
        float inv = 1.f / den;
        float* op = g_att + ((size_t)b_ * TT + gi) * DD + h * DH;
        op[lane]      = o0 * inv;
        op[lane + 32] = o1 * inv;
    }
}

// Empty alignment kernel: makes the replay period 4 launches so ncu's
// "-s 5 -c 1" (launch #5 = 5 mod 4 = 1) profiles attn_topk_kernel.
__global__ void nop_kernel() {}

// ============================================================================
// launch — kernel launches only; no CUDA API calls in the capture path.
// ============================================================================
extern "C" void kernel_launch(void* const* d_in, const int* in_sizes, int n_in,
                              void* d_out, int out_size)
{
    const float* x     = (const float*)d_in[0];   // (2,2048,1024)
    const float* w_qkv = (const float*)d_in[1];   // (3072,1024)
    const float* w_out = (const float*)d_in[2];   // (1024,1024)
    float* out = (float*)d_out;                   // (2,2048,1024)

    dim3 blk(256);
    // QKV projection + head-split scatter: M=4096, N=3072, K=1024
    sgemm_nt<<<dim3(3072 / 128, 4096 / 128), blk>>>(x, w_qkv, nullptr, 4096, 3072, 1024, 1);
    // fused causal scores + top-10 + fp64 re-rank + softmax + sparse AV
    attn_topk_kernel<<<dim3(BB * HH, TT / 32), blk>>>();
    // output projection: M=4096, N=1024, K=1024  (A = g_att via nullptr)
    sgemm_nt<<<dim3(1024 / 128, 4096 / 128), blk>>>(nullptr, w_out, out, 4096, 1024, 1024, 0);
    // ncu alignment (period-4 launch sequence -> launch #5 is the attn kernel)
    nop_kernel<<<1, 32>>>();
}